// round 13
// baseline (speedup 1.0000x reference)
#include <cuda_runtime.h>

#define B 64
#define BQ 8                // b's per work item (eighth of B)
#define NQ 8                // splits of the b dimension
#define C 1501
#define D 2048
#define D4 (D / 4)          // 512 float4 per row
#define TOT4 (C * D4)       // 768512 float4 per [C,D] tile
#define ALPHA 0.01f
#define EPS 1e-7f

// One block per (memory row c, eighth of the B repeat copies), grid (C, 8).
// Prologue minimized: the memory-row load issues first (latency hidden),
// then WARP 0 alone resolves dtype + last-write-wins owner from L2-hot
// global cls (reduce_max), broadcast via smem with a single barrier.
// The 64-iter per-thread scan survives only in the q==0 epilogue.
__global__ __launch_bounds__(512) void fused_kernel(
    const float4* __restrict__ x4,
    const float4* __restrict__ mem4,
    const int* __restrict__ cls_raw,
    float4* __restrict__ sel4,
    float4* __restrict__ rep4,
    float4* __restrict__ nm4) {
    const int c = blockIdx.x;
    const int q = blockIdx.y;          // 0..7
    const int t = threadIdx.x;         // 0..511

    __shared__ int s_cls[B];
    __shared__ int s_ow;
    __shared__ float s_red[16];

    // Independent of cls: issue immediately so latency overlaps the setup.
    const size_t row_off = (size_t)c * D4 + t;
    const float4 m = __ldg(mem4 + row_off);

    if (t < 32) {
        // Dtype detect: int64 little-endian odd words are high halves of
        // cls[0..31], all zero since 0 <= cls < 1501; int32: random ids.
        const int l = t;
        const int hi = cls_raw[2 * l + 1];
        const bool is64 = !__any_sync(0xffffffffu, hi != 0);
        const int e0 = is64 ? cls_raw[4 * l] : cls_raw[2 * l];
        const int e1 = is64 ? cls_raw[4 * l + 2] : cls_raw[2 * l + 1];
        s_cls[2 * l] = e0;
        s_cls[2 * l + 1] = e1;
        // last write wins -> max matching b
        int owl = -1;
        if (e0 == c) owl = 2 * l;
        if (e1 == c) owl = 2 * l + 1;
        owl = __reduce_max_sync(0xffffffffu, owl);
        if (l == 0) s_ow = owl;
    }
    __syncthreads();

    const int ow = s_ow;
    const float4 v = (ow >= 0) ? __ldg(x4 + (size_t)ow * D4 + t) : m;

    // Streaming writes: this block's BQ copies of tmp_memory[c].
    float4* dst = rep4 + (size_t)(q * BQ) * TOT4 + row_off;
#pragma unroll
    for (int b = 0; b < BQ; b++) {
        __stcs(dst, v);
        dst += TOT4;
    }

    if (q != 0) return;

    // selected[b] = ORIGINAL memory[cls[b]] for every matching b.
#pragma unroll
    for (int b = 0; b < B; b++)
        if (s_cls[b] == c) sel4[(size_t)b * D4 + t] = m;

    // EMA + L2 normalize for new_mem[c].
    float4 y;
    y.x = m.x * (1.f - ALPHA) + v.x * ALPHA;
    y.y = m.y * (1.f - ALPHA) + v.y * ALPHA;
    y.z = m.z * (1.f - ALPHA) + v.z * ALPHA;
    y.w = m.w * (1.f - ALPHA) + v.w * ALPHA;
    float ss = y.x * y.x + y.y * y.y + y.z * y.z + y.w * y.w;

#pragma unroll
    for (int off = 16; off > 0; off >>= 1)
        ss += __shfl_xor_sync(0xffffffffu, ss, off);
    if ((t & 31) == 0) s_red[t >> 5] = ss;
    __syncthreads();
    if (t < 32) {
        float u = (t < 16) ? s_red[t] : 0.f;
#pragma unroll
        for (int off = 8; off > 0; off >>= 1)
            u += __shfl_xor_sync(0xffffffffu, u, off);
        if (t == 0) s_red[0] = u;
    }
    __syncthreads();

    const float inv = 1.f / (sqrtf(s_red[0]) + EPS);
    y.x *= inv; y.y *= inv; y.z *= inv; y.w *= inv;
    nm4[row_off] = y;
}

extern "C" void kernel_launch(void* const* d_in, const int* in_sizes, int n_in,
                              void* d_out, int out_size) {
    const float* x = (const float*)d_in[0];
    const int* cls = (const int*)d_in[1];
    const float* memory = (const float*)d_in[2];
    float* out = (float*)d_out;

    float* sel = out;                    // [B, D]
    float* rep = out + (size_t)B * D;    // [B, C, D]
    float* nm = rep + (size_t)B * C * D; // [C, D]

    dim3 grid(C, NQ);
    fused_kernel<<<grid, 512>>>((const float4*)x, (const float4*)memory, cls,
                                (float4*)sel, (float4*)rep, (float4*)nm);
}

// round 14
// speedup vs baseline: 1.0052x; 1.0052x over previous
#include <cuda_runtime.h>

#define B 64
#define BQ 4                // b's per work item
#define NQ 16               // splits of the b dimension
#define C 1501
#define D 2048
#define D4 (D / 4)          // 512 float4 per row
#define TOT4 (C * D4)       // 768512 float4 per [C,D] tile
#define ALPHA 0.01f
#define EPS 1e-7f

// One block per (memory row c, 1/16 of the B repeat copies), grid (C, 16).
// Prologue: memory-row load issues first (latency hidden), warp 0 alone
// resolves dtype + last-write-wins owner (reduce_max) with one barrier.
__global__ __launch_bounds__(512) void fused_kernel(
    const float4* __restrict__ x4,
    const float4* __restrict__ mem4,
    const int* __restrict__ cls_raw,
    float4* __restrict__ sel4,
    float4* __restrict__ rep4,
    float4* __restrict__ nm4) {
    const int c = blockIdx.x;
    const int q = blockIdx.y;          // 0..NQ-1
    const int t = threadIdx.x;         // 0..511

    __shared__ int s_cls[B];
    __shared__ int s_ow;
    __shared__ float s_red[16];

    // Independent of cls: issue immediately so latency overlaps the setup.
    const size_t row_off = (size_t)c * D4 + t;
    const float4 m = __ldg(mem4 + row_off);

    if (t < 32) {
        // Dtype detect: int64 little-endian odd words are high halves of
        // cls[0..31], all zero since 0 <= cls < 1501; int32: random ids.
        const int l = t;
        const int hi = cls_raw[2 * l + 1];
        const bool is64 = !__any_sync(0xffffffffu, hi != 0);
        const int e0 = is64 ? cls_raw[4 * l] : cls_raw[2 * l];
        const int e1 = is64 ? cls_raw[4 * l + 2] : cls_raw[2 * l + 1];
        s_cls[2 * l] = e0;
        s_cls[2 * l + 1] = e1;
        // last write wins -> max matching b
        int owl = -1;
        if (e0 == c) owl = 2 * l;
        if (e1 == c) owl = 2 * l + 1;
        owl = __reduce_max_sync(0xffffffffu, owl);
        if (l == 0) s_ow = owl;
    }
    __syncthreads();

    const int ow = s_ow;
    const float4 v = (ow >= 0) ? __ldg(x4 + (size_t)ow * D4 + t) : m;

    // Streaming writes: this block's BQ copies of tmp_memory[c].
    float4* dst = rep4 + (size_t)(q * BQ) * TOT4 + row_off;
#pragma unroll
    for (int b = 0; b < BQ; b++) {
        __stcs(dst, v);
        dst += TOT4;
    }

    if (q != 0) return;

    // selected[b] = ORIGINAL memory[cls[b]] for every matching b.
#pragma unroll
    for (int b = 0; b < B; b++)
        if (s_cls[b] == c) sel4[(size_t)b * D4 + t] = m;

    // EMA + L2 normalize for new_mem[c].
    float4 y;
    y.x = m.x * (1.f - ALPHA) + v.x * ALPHA;
    y.y = m.y * (1.f - ALPHA) + v.y * ALPHA;
    y.z = m.z * (1.f - ALPHA) + v.z * ALPHA;
    y.w = m.w * (1.f - ALPHA) + v.w * ALPHA;
    float ss = y.x * y.x + y.y * y.y + y.z * y.z + y.w * y.w;

#pragma unroll
    for (int off = 16; off > 0; off >>= 1)
        ss += __shfl_xor_sync(0xffffffffu, ss, off);
    if ((t & 31) == 0) s_red[t >> 5] = ss;
    __syncthreads();
    if (t < 32) {
        float u = (t < 16) ? s_red[t] : 0.f;
#pragma unroll
        for (int off = 8; off > 0; off >>= 1)
            u += __shfl_xor_sync(0xffffffffu, u, off);
        if (t == 0) s_red[0] = u;
    }
    __syncthreads();

    const float inv = 1.f / (sqrtf(s_red[0]) + EPS);
    y.x *= inv; y.y *= inv; y.z *= inv; y.w *= inv;
    nm4[row_off] = y;
}

extern "C" void kernel_launch(void* const* d_in, const int* in_sizes, int n_in,
                              void* d_out, int out_size) {
    const float* x = (const float*)d_in[0];
    const int* cls = (const int*)d_in[1];
    const float* memory = (const float*)d_in[2];
    float* out = (float*)d_out;

    float* sel = out;                    // [B, D]
    float* rep = out + (size_t)B * D;    // [B, C, D]
    float* nm = rep + (size_t)B * C * D; // [C, D]

    dim3 grid(C, NQ);
    fused_kernel<<<grid, 512>>>((const float4*)x, (const float4*)memory, cls,
                                (float4*)sel, (float4*)rep, (float4*)nm);
}